// round 14
// baseline (speedup 1.0000x reference)
#include <cuda_runtime.h>
#include <math_constants.h>

// Problem constants (fixed shapes from setup_inputs)
#define BB 8
#define LP1 25
#define LL 24
#define TT 512
#define DD 1024
#define PP 128
#define TOPK 3

#define SPLIT1 16   // T-splits for score pass  -> 8*24*16 = 3072 blocks
#define SPLIT3 64   // T-splits for gather pass -> 8*64    = 512 blocks
#define FBLK   8    // p-slices per batch in k_final -> 64 blocks, 16 outputs each

// Output layout: flattened tuple in reference order, all fp32
#define OFF_PROJ   0
#define OFF_SCORES 1024
#define OFF_IDX    1216
#define OFF_SEL    1240

// k_final dynamic smem: w-slice 64KB + normed 4KB + part 1KB + reduce pads
#define SMEM_FINAL (65536 + 4096 + 1024 + 128)

// Scratch (device globals; allocation-free)
__device__ float g_score_partial[BB * LL * SPLIT1];
__device__ int   g_topk_idx[BB * TOPK];
__device__ float g_topk_val[BB * TOPK];
__device__ float g_max_partial[BB * SPLIT3 * DD];  // per-split max partials (2MB)
__device__ int   g_cnt;                            // last-block counter

// ---------------------------------------------------------------------------
// Kernel 1: per-(b,l,s) score partials over 32 t-rows each.
// The LAST block additionally does softmax + top-3.
// ---------------------------------------------------------------------------
__global__ __launch_bounds__(256) void k_scores(const float* __restrict__ x,
                                                const float* __restrict__ w_score,
                                                const float* __restrict__ b_score,
                                                float* __restrict__ out) {
    const int blk = blockIdx.x;           // 0 .. BB*LL*SPLIT1-1
    const int tid = threadIdx.x;

    const int s   = blk % SPLIT1;
    const int bl  = blk / SPLIT1;
    const int l   = bl % LL;
    const int b   = bl / LL;

    const float4* __restrict__ base =
        (const float4*)(x + ((size_t)b * LP1 + (size_t)(l + 1)) * TT * DD);
    const float4 w4 = ((const float4*)w_score)[tid];

    float acc = 0.f;
    const int t0 = s * (TT / SPLIT1);     // 32 rows per block
    #pragma unroll 8
    for (int t = t0; t < t0 + TT / SPLIT1; ++t) {
        float4 v = base[(size_t)t * (DD / 4) + tid];
        acc += v.x * w4.x + v.y * w4.y + v.z * w4.z + v.w * w4.w;
    }

    __shared__ float sm[256];
    sm[tid] = acc;
    __syncthreads();
    #pragma unroll
    for (int st = 128; st > 0; st >>= 1) {
        if (tid < st) sm[tid] += sm[tid + st];
        __syncthreads();
    }

    // publish partial, then last-block detection
    __shared__ int s_last;
    if (tid == 0) {
        g_score_partial[bl * SPLIT1 + s] = sm[0];
        __threadfence();
        int old = atomicAdd(&g_cnt, 1);
        s_last = (old == BB * LL * SPLIT1 - 1);
    }
    __syncthreads();
    if (!s_last) return;

    // ---- fused top-k (runs in exactly one block, after all partials) ----
    __threadfence();
    __shared__ float sc[BB * LL];
    if (tid < BB * LL) {
        float v = 0.f;
        #pragma unroll
        for (int i = 0; i < SPLIT1; ++i) v += g_score_partial[tid * SPLIT1 + i];
        v = v * (1.0f / (float)TT) + b_score[0];
        sc[tid] = v;
        out[OFF_SCORES + tid] = v;
    }
    __syncthreads();

    if (tid < BB) {
        const int bb = tid;
        float m = -CUDART_INF_F;
        #pragma unroll
        for (int l2 = 0; l2 < LL; ++l2) m = fmaxf(m, sc[bb * LL + l2]);
        float p[LL];
        float sum = 0.f;
        #pragma unroll
        for (int l2 = 0; l2 < LL; ++l2) { p[l2] = expf(sc[bb * LL + l2] - m); sum += p[l2]; }
        const float inv = 1.0f / sum;
        #pragma unroll
        for (int l2 = 0; l2 < LL; ++l2) p[l2] *= inv;

        bool used[LL];
        #pragma unroll
        for (int l2 = 0; l2 < LL; ++l2) used[l2] = false;

        for (int k = 0; k < TOPK; ++k) {
            int   best = 0;
            float bv   = -CUDART_INF_F;
            #pragma unroll
            for (int l2 = 0; l2 < LL; ++l2) {
                if (!used[l2] && p[l2] > bv) { bv = p[l2]; best = l2; }
            }
            used[best] = true;
            g_topk_idx[bb * TOPK + k] = best;
            g_topk_val[bb * TOPK + k] = bv;
            out[OFF_IDX + bb * TOPK + k] = (float)best;
        }
    }
    // reset counter for the next graph replay (deterministic)
    if (tid == 0) g_cnt = 0;
}

// ---------------------------------------------------------------------------
// Kernel 2: gather 3 selected layers -> write selected_layers output
// (streaming loads + stores), fused weighted sum + block-local max over T,
// DETERMINISTIC partial write (no atomics). B descending (L2-hot first).
// ---------------------------------------------------------------------------
__global__ __launch_bounds__(256) void k_gather(const float* __restrict__ x,
                                                float* __restrict__ out) {
    const int blk = blockIdx.x;             // 0 .. BB*SPLIT3-1
    const int s   = blk % SPLIT3;
    const int b   = (BB - 1) - blk / SPLIT3;   // descending: hot batches first
    const int tid = threadIdx.x;

    const int i0 = g_topk_idx[b * TOPK + 0];
    const int i1 = g_topk_idx[b * TOPK + 1];
    const int i2 = g_topk_idx[b * TOPK + 2];
    const float v0 = g_topk_val[b * TOPK + 0];
    const float v1 = g_topk_val[b * TOPK + 1];
    const float v2 = g_topk_val[b * TOPK + 2];

    const float4* __restrict__ p0 =
        (const float4*)(x + ((size_t)b * LP1 + (size_t)(i0 + 1)) * TT * DD);
    const float4* __restrict__ p1 =
        (const float4*)(x + ((size_t)b * LP1 + (size_t)(i1 + 1)) * TT * DD);
    const float4* __restrict__ p2 =
        (const float4*)(x + ((size_t)b * LP1 + (size_t)(i2 + 1)) * TT * DD);

    float* __restrict__ sel = out + OFF_SEL;
    float4* __restrict__ o0 = (float4*)(sel + ((size_t)b * TOPK + 0) * TT * DD);
    float4* __restrict__ o1 = (float4*)(sel + ((size_t)b * TOPK + 1) * TT * DD);
    float4* __restrict__ o2 = (float4*)(sel + ((size_t)b * TOPK + 2) * TT * DD);

    const int TPS = TT / SPLIT3;   // 8 rows per block
    float4 mx = make_float4(-CUDART_INF_F, -CUDART_INF_F, -CUDART_INF_F, -CUDART_INF_F);

    #pragma unroll
    for (int tt = 0; tt < TPS; ++tt) {
        const size_t off = (size_t)(s * TPS + tt) * (DD / 4) + tid;
        float4 a = __ldcs(&p0[off]);   // read-once: evict-first
        float4 c = __ldcs(&p1[off]);
        float4 e = __ldcs(&p2[off]);
        __stcs(&o0[off], a);
        __stcs(&o1[off], c);
        __stcs(&o2[off], e);
        float4 w;
        w.x = v0 * a.x + v1 * c.x + v2 * e.x;
        w.y = v0 * a.y + v1 * c.y + v2 * e.y;
        w.z = v0 * a.z + v1 * c.z + v2 * e.z;
        w.w = v0 * a.w + v1 * c.w + v2 * e.w;
        mx.x = fmaxf(mx.x, w.x);
        mx.y = fmaxf(mx.y, w.y);
        mx.z = fmaxf(mx.z, w.z);
        mx.w = fmaxf(mx.w, w.w);
    }

    // deterministic partial write — stays in L2, reduced inside k_final
    ((float4*)(g_max_partial + ((size_t)b * SPLIT3 + s) * DD))[tid] = mx;
}

// ---------------------------------------------------------------------------
// Kernel 3 (smem-staged, fused reduce): grid = BB*FBLK = 64, block = 256.
// Block (b, pb) computes outputs p in [16pb, 16pb+16).
// 1) issue w_proj slice loads (16 x LDG.128/thread, one DRAM round trip);
// 2) reduce this b's 64 max-partials (L2-hit float4 loads) -> pooled v;
// 3) LN; 4) stage w slice to smem; 5) GEMV from smem.
// ---------------------------------------------------------------------------
__global__ __launch_bounds__(256) void k_final(const float* __restrict__ gamma,
                                               const float* __restrict__ beta,
                                               const float* __restrict__ w_proj,
                                               const float* __restrict__ b_proj,
                                               float* __restrict__ out) {
    extern __shared__ float sbuf[];
    float* wsh    = sbuf;           // [1024][16] floats = 64KB
    float* normed = sbuf + 16384;   // [1024]
    float* part   = normed + DD;    // [256]
    float* red    = part + 256;     // [8]
    float* red2   = red + 8;        // [8]
    float* stats  = red2 + 8;       // [2]

    const int b    = blockIdx.x >> 3;     // FBLK = 8
    const int pb   = blockIdx.x & 7;
    const int tid  = threadIdx.x;
    const int lane = tid & 31, warp = tid >> 5;

    // --- 1) issue the w_proj slice loads (16 x LDG.128 per thread) ---
    float4 tmp[16];
    {
        const float* __restrict__ wbase = w_proj + pb * 16;
        #pragma unroll
        for (int j = 0; j < 16; ++j) {
            const int idx = tid + 256 * j;     // 0..4095
            const int row = idx >> 2;          // 0..1023 (d index)
            const int q   = idx & 3;           // 16B quarter within 64B row seg
            tmp[j] = *(const float4*)(wbase + (size_t)row * PP + q * 4);
        }
    }

    // --- 2) fused max-reduce over this b's 64 partials (L2 hits) ---
    float4 v = make_float4(-CUDART_INF_F, -CUDART_INF_F, -CUDART_INF_F, -CUDART_INF_F);
    {
        const float4* __restrict__ mp =
            (const float4*)(g_max_partial + (size_t)b * SPLIT3 * DD) + tid;
        #pragma unroll 8
        for (int s = 0; s < SPLIT3; ++s) {
            float4 t = mp[(size_t)s * (DD / 4)];
            v.x = fmaxf(v.x, t.x);
            v.y = fmaxf(v.y, t.y);
            v.z = fmaxf(v.z, t.z);
            v.w = fmaxf(v.w, t.w);
        }
    }

    // --- 3) LN ---
    {
        float s1 = v.x + v.y + v.z + v.w;
        float s2 = v.x * v.x + v.y * v.y + v.z * v.z + v.w * v.w;
        #pragma unroll
        for (int o = 16; o > 0; o >>= 1) {
            s1 += __shfl_down_sync(0xffffffffu, s1, o);
            s2 += __shfl_down_sync(0xffffffffu, s2, o);
        }
        if (lane == 0) { red[warp] = s1; red2[warp] = s2; }
        __syncthreads();
        if (tid == 0) {
            float t1 = 0.f, t2 = 0.f;
            #pragma unroll
            for (int i = 0; i < 8; ++i) { t1 += red[i]; t2 += red2[i]; }
            float mu  = t1 * (1.0f / (float)DD);
            float var = t2 * (1.0f / (float)DD) - mu * mu;
            stats[0] = mu;
            stats[1] = rsqrtf(var + 1e-5f);
        }
        __syncthreads();
        const float mu = stats[0], rstd = stats[1];
        const float4 g4  = ((const float4*)gamma)[tid];
        const float4 be4 = ((const float4*)beta)[tid];
        float4 n;
        n.x = (v.x - mu) * rstd * g4.x + be4.x;
        n.y = (v.y - mu) * rstd * g4.y + be4.y;
        n.z = (v.z - mu) * rstd * g4.z + be4.z;
        n.w = (v.w - mu) * rstd * g4.w + be4.w;
        ((float4*)normed)[tid] = n;
    }

    // --- 4) stage w slice to smem ---
    #pragma unroll
    for (int j = 0; j < 16; ++j) {
        const int idx = tid + 256 * j;
        *(float4*)(wsh + (size_t)idx * 4) = tmp[j];   // wsh[row][q*4..q*4+3]
    }
    __syncthreads();

    // --- 5) GEMV from smem: thread (g = tid>>4, p = tid&15) ---
    {
        const int p = tid & 15;
        const int g = tid >> 4;
        float a0 = 0.f, a1 = 0.f, a2 = 0.f, a3 = 0.f;
        #pragma unroll
        for (int k = 0; k < 64; k += 4) {
            const int r0 = g + 16 * (k + 0);
            const int r1 = g + 16 * (k + 1);
            const int r2 = g + 16 * (k + 2);
            const int r3 = g + 16 * (k + 3);
            a0 = fmaf(normed[r0], wsh[r0 * 16 + p], a0);
            a1 = fmaf(normed[r1], wsh[r1 * 16 + p], a1);
            a2 = fmaf(normed[r2], wsh[r2 * 16 + p], a2);
            a3 = fmaf(normed[r3], wsh[r3 * 16 + p], a3);
        }
        part[tid] = (a0 + a1) + (a2 + a3);
    }
    __syncthreads();
    if (tid < 16) {
        const int p = pb * 16 + tid;
        float acc = b_proj[p];
        #pragma unroll
        for (int g = 0; g < 16; ++g) acc += part[g * 16 + tid];
        out[OFF_PROJ + b * PP + p] = acc;
    }
}

// ---------------------------------------------------------------------------
// Launch (3 kernels)
// ---------------------------------------------------------------------------
extern "C" void kernel_launch(void* const* d_in, const int* in_sizes, int n_in,
                              void* d_out, int out_size) {
    const float* x       = (const float*)d_in[0];  // wav2vec_ft (8,25,512,1024)
    const float* w_score = (const float*)d_in[1];  // (1024,1)
    const float* b_score = (const float*)d_in[2];  // (1,)
    const float* ln_g    = (const float*)d_in[3];  // (1024,)
    const float* ln_b    = (const float*)d_in[4];  // (1024,)
    const float* w_proj  = (const float*)d_in[5];  // (1024,128)
    const float* b_proj  = (const float*)d_in[6];  // (128,)
    float* out = (float*)d_out;

    static bool attr_set = false;
    if (!attr_set) {
        cudaFuncSetAttribute(k_final, cudaFuncAttributeMaxDynamicSharedMemorySize,
                             SMEM_FINAL);
        attr_set = true;
    }

    k_scores<<<BB * LL * SPLIT1, 256>>>(x, w_score, b_score, out);
    k_gather<<<BB * SPLIT3, 256>>>(x, out);
    k_final<<<BB * FBLK, 256, SMEM_FINAL>>>(ln_g, ln_b, w_proj, b_proj, out);
}

// round 15
// speedup vs baseline: 1.0026x; 1.0026x over previous
#include <cuda_runtime.h>
#include <math_constants.h>

// Problem constants (fixed shapes from setup_inputs)
#define BB 8
#define LP1 25
#define LL 24
#define TT 512
#define DD 1024
#define PP 128
#define TOPK 3

#define SPLIT1 16   // T-splits for score pass  -> 8*24*16 = 3072 blocks
#define SPLIT3 64   // T-splits for gather pass -> 8*64    = 512 blocks
#define FBLK   8    // p-slices per batch in k_final -> 64 blocks, 16 outputs each

// Output layout: flattened tuple in reference order, all fp32
#define OFF_PROJ   0
#define OFF_SCORES 1024
#define OFF_IDX    1216
#define OFF_SEL    1240

// k_final dynamic smem: w-slice 64KB + normed 4KB + part 1KB + reduce pads
#define SMEM_FINAL (65536 + 4096 + 1024 + 128)

// Scratch (device globals; allocation-free)
__device__ float g_score_partial[BB * LL * SPLIT1];
__device__ int   g_topk_idx[BB * TOPK];
__device__ float g_topk_val[BB * TOPK];
__device__ float g_max_partial[BB * SPLIT3 * DD];  // per-split max partials (2MB)
__device__ float g_pooled[BB * DD];                // reduced max (32KB)
__device__ int   g_cnt;                            // scores last-block counter
__device__ int   g_cnt_b[BB];                      // gather per-b last-block counters

// ---------------------------------------------------------------------------
// Kernel 1: per-(b,l,s) score partials over 32 t-rows each.
// The LAST block additionally does softmax + top-3.
// ---------------------------------------------------------------------------
__global__ __launch_bounds__(256) void k_scores(const float* __restrict__ x,
                                                const float* __restrict__ w_score,
                                                const float* __restrict__ b_score,
                                                float* __restrict__ out) {
    const int blk = blockIdx.x;           // 0 .. BB*LL*SPLIT1-1
    const int tid = threadIdx.x;

    const int s   = blk % SPLIT1;
    const int bl  = blk / SPLIT1;
    const int l   = bl % LL;
    const int b   = bl / LL;

    const float4* __restrict__ base =
        (const float4*)(x + ((size_t)b * LP1 + (size_t)(l + 1)) * TT * DD);
    const float4 w4 = ((const float4*)w_score)[tid];

    float acc = 0.f;
    const int t0 = s * (TT / SPLIT1);     // 32 rows per block
    #pragma unroll 8
    for (int t = t0; t < t0 + TT / SPLIT1; ++t) {
        float4 v = base[(size_t)t * (DD / 4) + tid];
        acc += v.x * w4.x + v.y * w4.y + v.z * w4.z + v.w * w4.w;
    }

    __shared__ float sm[256];
    sm[tid] = acc;
    __syncthreads();
    #pragma unroll
    for (int st = 128; st > 0; st >>= 1) {
        if (tid < st) sm[tid] += sm[tid + st];
        __syncthreads();
    }

    // publish partial, then last-block detection
    __shared__ int s_last;
    if (tid == 0) {
        g_score_partial[bl * SPLIT1 + s] = sm[0];
        __threadfence();
        int old = atomicAdd(&g_cnt, 1);
        s_last = (old == BB * LL * SPLIT1 - 1);
    }
    __syncthreads();
    if (!s_last) return;

    // ---- fused top-k (runs in exactly one block, after all partials) ----
    __threadfence();
    __shared__ float sc[BB * LL];
    if (tid < BB * LL) {
        float v = 0.f;
        #pragma unroll
        for (int i = 0; i < SPLIT1; ++i) v += g_score_partial[tid * SPLIT1 + i];
        v = v * (1.0f / (float)TT) + b_score[0];
        sc[tid] = v;
        out[OFF_SCORES + tid] = v;
    }
    __syncthreads();

    if (tid < BB) {
        const int bb = tid;
        float m = -CUDART_INF_F;
        #pragma unroll
        for (int l2 = 0; l2 < LL; ++l2) m = fmaxf(m, sc[bb * LL + l2]);
        float p[LL];
        float sum = 0.f;
        #pragma unroll
        for (int l2 = 0; l2 < LL; ++l2) { p[l2] = expf(sc[bb * LL + l2] - m); sum += p[l2]; }
        const float inv = 1.0f / sum;
        #pragma unroll
        for (int l2 = 0; l2 < LL; ++l2) p[l2] *= inv;

        bool used[LL];
        #pragma unroll
        for (int l2 = 0; l2 < LL; ++l2) used[l2] = false;

        for (int k = 0; k < TOPK; ++k) {
            int   best = 0;
            float bv   = -CUDART_INF_F;
            #pragma unroll
            for (int l2 = 0; l2 < LL; ++l2) {
                if (!used[l2] && p[l2] > bv) { bv = p[l2]; best = l2; }
            }
            used[best] = true;
            g_topk_idx[bb * TOPK + k] = best;
            g_topk_val[bb * TOPK + k] = bv;
            out[OFF_IDX + bb * TOPK + k] = (float)best;
        }
    }
    // reset counter for the next graph replay (deterministic)
    if (tid == 0) g_cnt = 0;
}

// ---------------------------------------------------------------------------
// Kernel 2: gather 3 selected layers -> write selected_layers output
// (streaming stores), fused weighted sum + block-local max over T,
// deterministic partial write. The LAST block of each b (per-b counter)
// max-reduces that b's 64 partials into g_pooled (replaces k_reduce).
// B descending (L2-hot first).
// ---------------------------------------------------------------------------
__global__ __launch_bounds__(256) void k_gather(const float* __restrict__ x,
                                                float* __restrict__ out) {
    const int blk = blockIdx.x;             // 0 .. BB*SPLIT3-1
    const int s   = blk % SPLIT3;
    const int b   = (BB - 1) - blk / SPLIT3;   // descending: hot batches first
    const int tid = threadIdx.x;

    const int i0 = g_topk_idx[b * TOPK + 0];
    const int i1 = g_topk_idx[b * TOPK + 1];
    const int i2 = g_topk_idx[b * TOPK + 2];
    const float v0 = g_topk_val[b * TOPK + 0];
    const float v1 = g_topk_val[b * TOPK + 1];
    const float v2 = g_topk_val[b * TOPK + 2];

    const float4* __restrict__ p0 =
        (const float4*)(x + ((size_t)b * LP1 + (size_t)(i0 + 1)) * TT * DD);
    const float4* __restrict__ p1 =
        (const float4*)(x + ((size_t)b * LP1 + (size_t)(i1 + 1)) * TT * DD);
    const float4* __restrict__ p2 =
        (const float4*)(x + ((size_t)b * LP1 + (size_t)(i2 + 1)) * TT * DD);

    float* __restrict__ sel = out + OFF_SEL;
    float4* __restrict__ o0 = (float4*)(sel + ((size_t)b * TOPK + 0) * TT * DD);
    float4* __restrict__ o1 = (float4*)(sel + ((size_t)b * TOPK + 1) * TT * DD);
    float4* __restrict__ o2 = (float4*)(sel + ((size_t)b * TOPK + 2) * TT * DD);

    const int TPS = TT / SPLIT3;   // 8 rows per block
    float4 mx = make_float4(-CUDART_INF_F, -CUDART_INF_F, -CUDART_INF_F, -CUDART_INF_F);

    #pragma unroll
    for (int tt = 0; tt < TPS; ++tt) {
        const size_t off = (size_t)(s * TPS + tt) * (DD / 4) + tid;
        float4 a = p0[off];
        float4 c = p1[off];
        float4 e = p2[off];
        __stcs(&o0[off], a);
        __stcs(&o1[off], c);
        __stcs(&o2[off], e);
        float4 w;
        w.x = v0 * a.x + v1 * c.x + v2 * e.x;
        w.y = v0 * a.y + v1 * c.y + v2 * e.y;
        w.z = v0 * a.z + v1 * c.z + v2 * e.z;
        w.w = v0 * a.w + v1 * c.w + v2 * e.w;
        mx.x = fmaxf(mx.x, w.x);
        mx.y = fmaxf(mx.y, w.y);
        mx.z = fmaxf(mx.z, w.z);
        mx.w = fmaxf(mx.w, w.w);
    }

    // deterministic partial write (L2-resident)
    ((float4*)(g_max_partial + ((size_t)b * SPLIT3 + s) * DD))[tid] = mx;

    // last block of this b reduces the 64 partials -> g_pooled[b]
    __shared__ int s_last;
    if (tid == 0) {
        __threadfence();
        int old = atomicAdd(&g_cnt_b[b], 1);
        s_last = (old == SPLIT3 - 1);
    }
    __syncthreads();
    if (!s_last) return;
    __threadfence();

    float4 v = make_float4(-CUDART_INF_F, -CUDART_INF_F, -CUDART_INF_F, -CUDART_INF_F);
    const float4* __restrict__ mp =
        (const float4*)(g_max_partial + (size_t)b * SPLIT3 * DD) + tid;
    #pragma unroll 8
    for (int ss = 0; ss < SPLIT3; ++ss) {
        float4 t = mp[(size_t)ss * (DD / 4)];
        v.x = fmaxf(v.x, t.x);
        v.y = fmaxf(v.y, t.y);
        v.z = fmaxf(v.z, t.z);
        v.w = fmaxf(v.w, t.w);
    }
    ((float4*)(g_pooled + (size_t)b * DD))[tid] = v;

    if (tid == 0) g_cnt_b[b] = 0;   // reset for next graph replay
}

// ---------------------------------------------------------------------------
// Kernel 3 (smem-staged, identical to R13 best): grid = BB*FBLK = 64,
// block = 256. Block (b, pb) computes outputs p in [16pb, 16pb+16).
// ---------------------------------------------------------------------------
__global__ __launch_bounds__(256) void k_final(const float* __restrict__ gamma,
                                               const float* __restrict__ beta,
                                               const float* __restrict__ w_proj,
                                               const float* __restrict__ b_proj,
                                               float* __restrict__ out) {
    extern __shared__ float sbuf[];
    float* wsh    = sbuf;           // [1024][16] floats = 64KB
    float* normed = sbuf + 16384;   // [1024]
    float* part   = normed + DD;    // [256]
    float* red    = part + 256;     // [8]
    float* red2   = red + 8;        // [8]
    float* stats  = red2 + 8;       // [2]

    const int b    = blockIdx.x >> 3;     // FBLK = 8
    const int pb   = blockIdx.x & 7;
    const int tid  = threadIdx.x;
    const int lane = tid & 31, warp = tid >> 5;

    // --- 1) issue the w_proj slice loads (16 x LDG.128 per thread) ---
    float4 tmp[16];
    {
        const float* __restrict__ wbase = w_proj + pb * 16;
        #pragma unroll
        for (int j = 0; j < 16; ++j) {
            const int idx = tid + 256 * j;     // 0..4095
            const int row = idx >> 2;          // 0..1023 (d index)
            const int q   = idx & 3;           // 16B quarter within 64B row seg
            tmp[j] = *(const float4*)(wbase + (size_t)row * PP + q * 4);
        }
    }

    // --- 2) LN (overlaps the DRAM round trip above) ---
    {
        const float4 v = ((const float4*)(g_pooled + (size_t)b * DD))[tid];

        float s1 = v.x + v.y + v.z + v.w;
        float s2 = v.x * v.x + v.y * v.y + v.z * v.z + v.w * v.w;
        #pragma unroll
        for (int o = 16; o > 0; o >>= 1) {
            s1 += __shfl_down_sync(0xffffffffu, s1, o);
            s2 += __shfl_down_sync(0xffffffffu, s2, o);
        }
        if (lane == 0) { red[warp] = s1; red2[warp] = s2; }
        __syncthreads();
        if (tid == 0) {
            float t1 = 0.f, t2 = 0.f;
            #pragma unroll
            for (int i = 0; i < 8; ++i) { t1 += red[i]; t2 += red2[i]; }
            float mu  = t1 * (1.0f / (float)DD);
            float var = t2 * (1.0f / (float)DD) - mu * mu;
            stats[0] = mu;
            stats[1] = rsqrtf(var + 1e-5f);
        }
        __syncthreads();
        const float mu = stats[0], rstd = stats[1];
        const float4 g4  = ((const float4*)gamma)[tid];
        const float4 be4 = ((const float4*)beta)[tid];
        float4 n;
        n.x = (v.x - mu) * rstd * g4.x + be4.x;
        n.y = (v.y - mu) * rstd * g4.y + be4.y;
        n.z = (v.z - mu) * rstd * g4.z + be4.z;
        n.w = (v.w - mu) * rstd * g4.w + be4.w;
        ((float4*)normed)[tid] = n;
    }

    // --- 3) stage w slice to smem ---
    #pragma unroll
    for (int j = 0; j < 16; ++j) {
        const int idx = tid + 256 * j;
        *(float4*)(wsh + (size_t)idx * 4) = tmp[j];   // wsh[row][q*4..q*4+3]
    }
    __syncthreads();

    // --- 4) GEMV from smem: thread (g = tid>>4, p = tid&15) ---
    {
        const int p = tid & 15;
        const int g = tid >> 4;
        float a0 = 0.f, a1 = 0.f, a2 = 0.f, a3 = 0.f;
        #pragma unroll
        for (int k = 0; k < 64; k += 4) {
            const int r0 = g + 16 * (k + 0);
            const int r1 = g + 16 * (k + 1);
            const int r2 = g + 16 * (k + 2);
            const int r3 = g + 16 * (k + 3);
            a0 = fmaf(normed[r0], wsh[r0 * 16 + p], a0);
            a1 = fmaf(normed[r1], wsh[r1 * 16 + p], a1);
            a2 = fmaf(normed[r2], wsh[r2 * 16 + p], a2);
            a3 = fmaf(normed[r3], wsh[r3 * 16 + p], a3);
        }
        part[tid] = (a0 + a1) + (a2 + a3);
    }
    __syncthreads();
    if (tid < 16) {
        const int p = pb * 16 + tid;
        float acc = b_proj[p];
        #pragma unroll
        for (int g = 0; g < 16; ++g) acc += part[g * 16 + tid];
        out[OFF_PROJ + b * PP + p] = acc;
    }
}

// ---------------------------------------------------------------------------
// Launch (3 kernels)
// ---------------------------------------------------------------------------
extern "C" void kernel_launch(void* const* d_in, const int* in_sizes, int n_in,
                              void* d_out, int out_size) {
    const float* x       = (const float*)d_in[0];  // wav2vec_ft (8,25,512,1024)
    const float* w_score = (const float*)d_in[1];  // (1024,1)
    const float* b_score = (const float*)d_in[2];  // (1,)
    const float* ln_g    = (const float*)d_in[3];  // (1024,)
    const float* ln_b    = (const float*)d_in[4];  // (1024,)
    const float* w_proj  = (const float*)d_in[5];  // (1024,128)
    const float* b_proj  = (const float*)d_in[6];  // (128,)
    float* out = (float*)d_out;

    static bool attr_set = false;
    if (!attr_set) {
        cudaFuncSetAttribute(k_final, cudaFuncAttributeMaxDynamicSharedMemorySize,
                             SMEM_FINAL);
        attr_set = true;
    }

    k_scores<<<BB * LL * SPLIT1, 256>>>(x, w_score, b_score, out);
    k_gather<<<BB * SPLIT3, 256>>>(x, out);
    k_final<<<BB * FBLK, 256, SMEM_FINAL>>>(ln_g, ln_b, w_proj, b_proj, out);
}

// round 16
// speedup vs baseline: 1.0296x; 1.0268x over previous
#include <cuda_runtime.h>
#include <math_constants.h>

// Problem constants (fixed shapes from setup_inputs)
#define BB 8
#define LP1 25
#define LL 24
#define TT 512
#define DD 1024
#define PP 128
#define TOPK 3

#define SPLIT1 16   // T-splits for score pass  -> 8*24*16 = 3072 blocks
#define SPLIT3 64   // T-splits for gather pass -> 8*64    = 512 blocks
#define FBLK   8    // p-slices per batch in k_final -> 64 blocks, 16 outputs each

// Output layout: flattened tuple in reference order, all fp32
#define OFF_PROJ   0
#define OFF_SCORES 1024
#define OFF_IDX    1216
#define OFF_SEL    1240

// k_final dynamic smem: w-slice 64KB + normed 4KB + part 1KB + reduce pads
#define SMEM_FINAL (65536 + 4096 + 1024 + 128)

// Scratch (device globals; allocation-free)
__device__ float g_score_partial[BB * LL * SPLIT1];
__device__ int   g_topk_idx[BB * TOPK];
__device__ float g_topk_val[BB * TOPK];
__device__ float g_max_partial[BB * SPLIT3 * DD];  // per-split max partials (2MB)
__device__ float g_pooled[BB * DD];                // reduced max (32KB)
__device__ int   g_cnt;                            // last-block counter

// ---------------------------------------------------------------------------
// Kernel 1: per-(b,l,s) score partials over 32 t-rows each.
// The LAST block additionally does softmax + top-3.
// ---------------------------------------------------------------------------
__global__ __launch_bounds__(256) void k_scores(const float* __restrict__ x,
                                                const float* __restrict__ w_score,
                                                const float* __restrict__ b_score,
                                                float* __restrict__ out) {
    const int blk = blockIdx.x;           // 0 .. BB*LL*SPLIT1-1
    const int tid = threadIdx.x;

    const int s   = blk % SPLIT1;
    const int bl  = blk / SPLIT1;
    const int l   = bl % LL;
    const int b   = bl / LL;

    const float4* __restrict__ base =
        (const float4*)(x + ((size_t)b * LP1 + (size_t)(l + 1)) * TT * DD);
    const float4 w4 = ((const float4*)w_score)[tid];

    float acc = 0.f;
    const int t0 = s * (TT / SPLIT1);     // 32 rows per block
    #pragma unroll 8
    for (int t = t0; t < t0 + TT / SPLIT1; ++t) {
        float4 v = base[(size_t)t * (DD / 4) + tid];
        acc += v.x * w4.x + v.y * w4.y + v.z * w4.z + v.w * w4.w;
    }

    __shared__ float sm[256];
    sm[tid] = acc;
    __syncthreads();
    #pragma unroll
    for (int st = 128; st > 0; st >>= 1) {
        if (tid < st) sm[tid] += sm[tid + st];
        __syncthreads();
    }

    // publish partial, then last-block detection
    __shared__ int s_last;
    if (tid == 0) {
        g_score_partial[bl * SPLIT1 + s] = sm[0];
        __threadfence();
        int old = atomicAdd(&g_cnt, 1);
        s_last = (old == BB * LL * SPLIT1 - 1);
    }
    __syncthreads();
    if (!s_last) return;

    // ---- fused top-k (runs in exactly one block, after all partials) ----
    __threadfence();
    __shared__ float sc[BB * LL];
    if (tid < BB * LL) {
        float v = 0.f;
        #pragma unroll
        for (int i = 0; i < SPLIT1; ++i) v += g_score_partial[tid * SPLIT1 + i];
        v = v * (1.0f / (float)TT) + b_score[0];
        sc[tid] = v;
        out[OFF_SCORES + tid] = v;
    }
    __syncthreads();

    if (tid < BB) {
        const int bb = tid;
        float m = -CUDART_INF_F;
        #pragma unroll
        for (int l2 = 0; l2 < LL; ++l2) m = fmaxf(m, sc[bb * LL + l2]);
        float p[LL];
        float sum = 0.f;
        #pragma unroll
        for (int l2 = 0; l2 < LL; ++l2) { p[l2] = expf(sc[bb * LL + l2] - m); sum += p[l2]; }
        const float inv = 1.0f / sum;
        #pragma unroll
        for (int l2 = 0; l2 < LL; ++l2) p[l2] *= inv;

        bool used[LL];
        #pragma unroll
        for (int l2 = 0; l2 < LL; ++l2) used[l2] = false;

        for (int k = 0; k < TOPK; ++k) {
            int   best = 0;
            float bv   = -CUDART_INF_F;
            #pragma unroll
            for (int l2 = 0; l2 < LL; ++l2) {
                if (!used[l2] && p[l2] > bv) { bv = p[l2]; best = l2; }
            }
            used[best] = true;
            g_topk_idx[bb * TOPK + k] = best;
            g_topk_val[bb * TOPK + k] = bv;
            out[OFF_IDX + bb * TOPK + k] = (float)best;
        }
    }
    // reset counter for the next graph replay (deterministic)
    if (tid == 0) g_cnt = 0;
}

// ---------------------------------------------------------------------------
// Kernel 2: gather 3 selected layers -> write selected_layers output
// (streaming stores), fused weighted sum + block-local max over T,
// DETERMINISTIC partial write (no atomics). B descending (L2-hot first).
// ---------------------------------------------------------------------------
__global__ __launch_bounds__(256) void k_gather(const float* __restrict__ x,
                                                float* __restrict__ out) {
    const int blk = blockIdx.x;             // 0 .. BB*SPLIT3-1
    const int s   = blk % SPLIT3;
    const int b   = (BB - 1) - blk / SPLIT3;   // descending: hot batches first
    const int tid = threadIdx.x;

    const int i0 = g_topk_idx[b * TOPK + 0];
    const int i1 = g_topk_idx[b * TOPK + 1];
    const int i2 = g_topk_idx[b * TOPK + 2];
    const float v0 = g_topk_val[b * TOPK + 0];
    const float v1 = g_topk_val[b * TOPK + 1];
    const float v2 = g_topk_val[b * TOPK + 2];

    const float4* __restrict__ p0 =
        (const float4*)(x + ((size_t)b * LP1 + (size_t)(i0 + 1)) * TT * DD);
    const float4* __restrict__ p1 =
        (const float4*)(x + ((size_t)b * LP1 + (size_t)(i1 + 1)) * TT * DD);
    const float4* __restrict__ p2 =
        (const float4*)(x + ((size_t)b * LP1 + (size_t)(i2 + 1)) * TT * DD);

    float* __restrict__ sel = out + OFF_SEL;
    float4* __restrict__ o0 = (float4*)(sel + ((size_t)b * TOPK + 0) * TT * DD);
    float4* __restrict__ o1 = (float4*)(sel + ((size_t)b * TOPK + 1) * TT * DD);
    float4* __restrict__ o2 = (float4*)(sel + ((size_t)b * TOPK + 2) * TT * DD);

    const int TPS = TT / SPLIT3;   // 8 rows per block
    float4 mx = make_float4(-CUDART_INF_F, -CUDART_INF_F, -CUDART_INF_F, -CUDART_INF_F);

    #pragma unroll
    for (int tt = 0; tt < TPS; ++tt) {
        const size_t off = (size_t)(s * TPS + tt) * (DD / 4) + tid;
        float4 a = p0[off];
        float4 c = p1[off];
        float4 e = p2[off];
        __stcs(&o0[off], a);
        __stcs(&o1[off], c);
        __stcs(&o2[off], e);
        float4 w;
        w.x = v0 * a.x + v1 * c.x + v2 * e.x;
        w.y = v0 * a.y + v1 * c.y + v2 * e.y;
        w.z = v0 * a.z + v1 * c.z + v2 * e.z;
        w.w = v0 * a.w + v1 * c.w + v2 * e.w;
        mx.x = fmaxf(mx.x, w.x);
        mx.y = fmaxf(mx.y, w.y);
        mx.z = fmaxf(mx.z, w.z);
        mx.w = fmaxf(mx.w, w.w);
    }

    // deterministic partial write — stays in L2, reduced by k_reduce
    ((float4*)(g_max_partial + ((size_t)b * SPLIT3 + s) * DD))[tid] = mx;
}

// ---------------------------------------------------------------------------
// Kernel 3: reduce 64 partials -> g_pooled. 32 blocks x 256 threads;
// thread owns one (b,d): 64 coalesced-stride loads, unrolled (high MLP).
// ---------------------------------------------------------------------------
__global__ __launch_bounds__(256) void k_reduce() {
    const int idx = blockIdx.x * 256 + threadIdx.x;   // 0..8191
    const int b   = idx >> 10;
    const int d   = idx & (DD - 1);
    const float* __restrict__ mp = g_max_partial + (size_t)b * SPLIT3 * DD + d;
    float m = -CUDART_INF_F;
    #pragma unroll 16
    for (int s = 0; s < SPLIT3; ++s)
        m = fmaxf(m, mp[(size_t)s * DD]);
    g_pooled[idx] = m;
}

// ---------------------------------------------------------------------------
// Kernel 4 (smem-staged): grid = BB*FBLK = 64, block = 256.
// Block (b, pb) computes outputs p in [16pb, 16pb+16).
// ---------------------------------------------------------------------------
__global__ __launch_bounds__(256) void k_final(const float* __restrict__ gamma,
                                               const float* __restrict__ beta,
                                               const float* __restrict__ w_proj,
                                               const float* __restrict__ b_proj,
                                               float* __restrict__ out) {
    extern __shared__ float sbuf[];
    float* wsh    = sbuf;           // [1024][16] floats = 64KB
    float* normed = sbuf + 16384;   // [1024]
    float* part   = normed + DD;    // [256]
    float* red    = part + 256;     // [8]
    float* red2   = red + 8;        // [8]
    float* stats  = red2 + 8;       // [2]

    const int b    = blockIdx.x >> 3;     // FBLK = 8
    const int pb   = blockIdx.x & 7;
    const int tid  = threadIdx.x;
    const int lane = tid & 31, warp = tid >> 5;

    // --- 1) issue the w_proj slice loads (16 x LDG.128 per thread) ---
    float4 tmp[16];
    {
        const float* __restrict__ wbase = w_proj + pb * 16;
        #pragma unroll
        for (int j = 0; j < 16; ++j) {
            const int idx = tid + 256 * j;     // 0..4095
            const int row = idx >> 2;          // 0..1023 (d index)
            const int q   = idx & 3;           // 16B quarter within 64B row seg
            tmp[j] = *(const float4*)(wbase + (size_t)row * PP + q * 4);
        }
    }

    // --- 2) LN (overlaps the DRAM round trip above) ---
    {
        const float4 v = ((const float4*)(g_pooled + (size_t)b * DD))[tid];

        float s1 = v.x + v.y + v.z + v.w;
        float s2 = v.x * v.x + v.y * v.y + v.z * v.z + v.w * v.w;
        #pragma unroll
        for (int o = 16; o > 0; o >>= 1) {
            s1 += __shfl_down_sync(0xffffffffu, s1, o);
            s2 += __shfl_down_sync(0xffffffffu, s2, o);
        }
        if (lane == 0) { red[warp] = s1; red2[warp] = s2; }
        __syncthreads();
        if (tid == 0) {
            float t1 = 0.f, t2 = 0.f;
            #pragma unroll
            for (int i = 0; i < 8; ++i) { t1 += red[i]; t2 += red2[i]; }
            float mu  = t1 * (1.0f / (float)DD);
            float var = t2 * (1.0f / (float)DD) - mu * mu;
            stats[0] = mu;
            stats[1] = rsqrtf(var + 1e-5f);
        }
        __syncthreads();
        const float mu = stats[0], rstd = stats[1];
        const float4 g4  = ((const float4*)gamma)[tid];
        const float4 be4 = ((const float4*)beta)[tid];
        float4 n;
        n.x = (v.x - mu) * rstd * g4.x + be4.x;
        n.y = (v.y - mu) * rstd * g4.y + be4.y;
        n.z = (v.z - mu) * rstd * g4.z + be4.z;
        n.w = (v.w - mu) * rstd * g4.w + be4.w;
        ((float4*)normed)[tid] = n;
    }

    // --- 3) stage w slice to smem ---
    #pragma unroll
    for (int j = 0; j < 16; ++j) {
        const int idx = tid + 256 * j;
        *(float4*)(wsh + (size_t)idx * 4) = tmp[j];   // wsh[row][q*4..q*4+3]
    }
    __syncthreads();

    // --- 4) GEMV from smem: thread (g = tid>>4, p = tid&15) ---
    {
        const int p = tid & 15;
        const int g = tid >> 4;
        float a0 = 0.f, a1 = 0.f, a2 = 0.f, a3 = 0.f;
        #pragma unroll
        for (int k = 0; k < 64; k += 4) {
            const int r0 = g + 16 * (k + 0);
            const int r1 = g + 16 * (k + 1);
            const int r2 = g + 16 * (k + 2);
            const int r3 = g + 16 * (k + 3);
            a0 = fmaf(normed[r0], wsh[r0 * 16 + p], a0);
            a1 = fmaf(normed[r1], wsh[r1 * 16 + p], a1);
            a2 = fmaf(normed[r2], wsh[r2 * 16 + p], a2);
            a3 = fmaf(normed[r3], wsh[r3 * 16 + p], a3);
        }
        part[tid] = (a0 + a1) + (a2 + a3);
    }
    __syncthreads();
    if (tid < 16) {
        const int p = pb * 16 + tid;
        float acc = b_proj[p];
        #pragma unroll
        for (int g = 0; g < 16; ++g) acc += part[g * 16 + tid];
        out[OFF_PROJ + b * PP + p] = acc;
    }
}

// ---------------------------------------------------------------------------
// Launch (4 kernels — the measured-best R13 configuration)
// ---------------------------------------------------------------------------
extern "C" void kernel_launch(void* const* d_in, const int* in_sizes, int n_in,
                              void* d_out, int out_size) {
    const float* x       = (const float*)d_in[0];  // wav2vec_ft (8,25,512,1024)
    const float* w_score = (const float*)d_in[1];  // (1024,1)
    const float* b_score = (const float*)d_in[2];  // (1,)
    const float* ln_g    = (const float*)d_in[3];  // (1024,)
    const float* ln_b    = (const float*)d_in[4];  // (1024,)
    const float* w_proj  = (const float*)d_in[5];  // (1024,128)
    const float* b_proj  = (const float*)d_in[6];  // (128,)
    float* out = (float*)d_out;

    static bool attr_set = false;
    if (!attr_set) {
        cudaFuncSetAttribute(k_final, cudaFuncAttributeMaxDynamicSharedMemorySize,
                             SMEM_FINAL);
        attr_set = true;
    }

    k_scores<<<BB * LL * SPLIT1, 256>>>(x, w_score, b_score, out);
    k_gather<<<BB * SPLIT3, 256>>>(x, out);
    k_reduce<<<32, 256>>>();
    k_final<<<BB * FBLK, 256, SMEM_FINAL>>>(ln_g, ln_b, w_proj, b_proj, out);
}